// round 11
// baseline (speedup 1.0000x reference)
#include <cuda_runtime.h>

#define Hh 32
#define Bb 64
#define Tt 16384
#define CHUNK 16
#define NCHUNK (Tt / CHUNK)
#define RSZ (CHUNK * Hh * 4)      /* one ring buffer: 2048 B */

__device__ __forceinline__ unsigned long long pk2(float lo, float hi) {
    unsigned long long d; asm("mov.b64 %0,{%1,%2};" : "=l"(d) : "f"(lo), "f"(hi)); return d;
}
__device__ __forceinline__ void upk2(unsigned long long v, float& lo, float& hi) {
    asm("mov.b64 {%0,%1},%2;" : "=f"(lo), "=f"(hi) : "l"(v));
}
__device__ __forceinline__ unsigned long long ffma2(unsigned long long a, unsigned long long b, unsigned long long c) {
    unsigned long long d; asm("fma.rn.f32x2 %0,%1,%2,%3;" : "=l"(d) : "l"(a), "l"(b), "l"(c)); return d;
}
__device__ __forceinline__ unsigned long long fadd2(unsigned long long a, unsigned long long b) {
    unsigned long long d; asm("add.rn.f32x2 %0,%1,%2;" : "=l"(d) : "l"(a), "l"(b)); return d;
}
__device__ __forceinline__ float red2(unsigned long long a0, unsigned long long a1,
                                      unsigned long long a2, unsigned long long a3) {
    unsigned long long s = fadd2(fadd2(a0, a1), fadd2(a2, a3));
    float lo, hi; upk2(s, lo, hi);
    return lo + hi;
}

// hardware tanh (MUFU.TANH)
__device__ __forceinline__ float htanh(float z) {
    float t; asm("tanh.approx.f32 %0,%1;" : "=f"(t) : "f"(z));
    return t;
}

#define LOADPN(sa_, P) \
    unsigned long long P##0,P##1,P##2,P##3,P##4,P##5,P##6,P##7,P##8,P##9,P##a,P##b,P##c,P##d,P##e,P##f; \
    asm volatile("ld.shared.v2.u64 {%0,%1},[%2];"    : "=l"(P##0), "=l"(P##1) : "r"(sa_)); \
    asm volatile("ld.shared.v2.u64 {%0,%1},[%2+16];" : "=l"(P##2), "=l"(P##3) : "r"(sa_)); \
    asm volatile("ld.shared.v2.u64 {%0,%1},[%2+32];" : "=l"(P##4), "=l"(P##5) : "r"(sa_)); \
    asm volatile("ld.shared.v2.u64 {%0,%1},[%2+48];" : "=l"(P##6), "=l"(P##7) : "r"(sa_)); \
    asm volatile("ld.shared.v2.u64 {%0,%1},[%2+64];" : "=l"(P##8), "=l"(P##9) : "r"(sa_)); \
    asm volatile("ld.shared.v2.u64 {%0,%1},[%2+80];" : "=l"(P##a), "=l"(P##b) : "r"(sa_)); \
    asm volatile("ld.shared.v2.u64 {%0,%1},[%2+96];" : "=l"(P##c), "=l"(P##d) : "r"(sa_)); \
    asm volatile("ld.shared.v2.u64 {%0,%1},[%2+112];": "=l"(P##e), "=l"(P##f) : "r"(sa_));

#define DOT16N(w2, seed, res, P) { \
    unsigned long long a0 = pk2(seed, 0.f), a1 = 0ull, a2 = 0ull, a3 = 0ull; \
    a0 = ffma2(w2[0],  P##0, a0); a1 = ffma2(w2[1],  P##1, a1); \
    a2 = ffma2(w2[2],  P##2, a2); a3 = ffma2(w2[3],  P##3, a3); \
    a0 = ffma2(w2[4],  P##4, a0); a1 = ffma2(w2[5],  P##5, a1); \
    a2 = ffma2(w2[6],  P##6, a2); a3 = ffma2(w2[7],  P##7, a3); \
    a0 = ffma2(w2[8],  P##8, a0); a1 = ffma2(w2[9],  P##9, a1); \
    a2 = ffma2(w2[10], P##a, a2); a3 = ffma2(w2[11], P##b, a3); \
    a0 = ffma2(w2[12], P##c, a0); a1 = ffma2(w2[13], P##d, a1); \
    a2 = ffma2(w2[14], P##e, a2); a3 = ffma2(w2[15], P##f, a3); \
    res = red2(a0, a1, a2, a3); }

#define STSF(addr, val) asm volatile("st.shared.f32 [%0], %1;" :: "r"(addr), "f"(val))
#define LDSF(val, addr) asm volatile("ld.shared.f32 %0, [%1];" : "=f"(val) : "r"(addr))

__device__ __forceinline__ void load_w2(const float* __restrict__ W, int lane,
                                        unsigned long long* w2) {
    #pragma unroll
    for (int k = 0; k < 16; ++k)
        w2[k] = pk2(W[lane * Hh + 2 * k], W[lane * Hh + 2 * k + 1]);
}

__global__ __launch_bounds__(96, 1) void rnn_pipe_kernel(
    const float* __restrict__ x,        const float* __restrict__ h_state,
    const float* __restrict__ W_ih0,    const float* __restrict__ W_hh0,
    const float* __restrict__ b_ih0,    const float* __restrict__ b_hh0,
    const float* __restrict__ W_ih1,    const float* __restrict__ W_hh1,
    const float* __restrict__ b_ih1,    const float* __restrict__ b_hh1,
    const float* __restrict__ W_out,    const float* __restrict__ b_out,
    float* __restrict__ out)
{
    __shared__ __align__(16) float sh0u[2][CHUNK][Hh], sh0v[2][CHUNK][Hh]; // A ring/exchange
    __shared__ __align__(16) float suu [2][CHUNK][Hh], suv [2][CHUNK][Hh]; // B2 -> B1 (bias1 folded)
    __shared__ float sh1u[2][CHUNK][Hh + 1], sh1v[2][CHUNK][Hh + 1];       // B1 -> out (padded)
    __shared__ __align__(16) float hx1u[Hh], hx1v[Hh];                     // B1 exchanges

    const int bu   = 2 * blockIdx.x;
    const int bv   = bu + 1;
    const int lane = threadIdx.x & 31;
    const int wid  = threadIdx.x >> 5;
    const unsigned FULL = 0xffffffffu;

    if (wid == 0) {
        // ---- Warp A: layer-0, two sequences, loads-first schedule ----
        unsigned long long w2[16];
        load_w2(W_hh0, lane, w2);
        const float wi    = W_ih0[lane];
        const float bias0 = b_ih0[lane] + b_hh0[lane];
        float hU = h_state[bu * Hh + lane];
        float hV = h_state[bv * Hh + lane];
        unsigned int s0u = (unsigned int)__cvta_generic_to_shared(sh0u);
        unsigned int s0v = (unsigned int)__cvta_generic_to_shared(sh0v);

        // Seed exchange rows (buf1, last row) — overwritten in chunk 1 before B2 reads buf1.
        unsigned int rdU = s0u + RSZ + (CHUNK - 1) * (Hh * 4);
        unsigned int rdV = s0v + RSZ + (CHUNK - 1) * (Hh * 4);
        STSF(rdU + lane * 4, hU);
        STSF(rdV + lane * 4, hV);

        const float* xbU = x + (size_t)bu * Tt;
        const float* xbV = x + (size_t)bv * Tt;
        float xcU = xbU[lane & 15], xcV = xbV[lane & 15];
        for (int g = 0; g < NCHUNK + 3; ++g) {
            if (g < NCHUNK) {
                float xnU = (g + 1 < NCHUNK) ? xbU[(g + 1) * CHUNK + (lane & 15)] : 0.f;
                float xnV = (g + 1 < NCHUNK) ? xbV[(g + 1) * CHUNK + (lane & 15)] : 0.f;
                unsigned int wrU = s0u + (g & 1) * RSZ;
                unsigned int wrV = s0v + (g & 1) * RSZ;
                #pragma unroll 8
                for (int s = 0; s < CHUNK; ++s) {
                    float xtU = fmaf(__shfl_sync(FULL, xcU, s), wi, bias0); // off-chain
                    float xtV = fmaf(__shfl_sync(FULL, xcV, s), wi, bias0);
                    LOADPN(rdU, U);                 // both load bursts in flight
                    LOADPN(rdV, V);                 // BEFORE either dot can stall
                    float zU; DOT16N(w2, xtU, zU, U);
                    float zV; DOT16N(w2, xtV, zV, V);
                    hU = htanh(zU);
                    hV = htanh(zV);
                    STSF(wrU + lane * 4, hU);       // ring write = exchange write
                    STSF(wrV + lane * 4, hV);
                    rdU = wrU; rdV = wrV;
                    wrU += Hh * 4; wrV += Hh * 4;
                }
                xcU = xnU; xcV = xnV;
            }
            __syncthreads();
        }
        out[(size_t)Bb * Tt + bu * Hh + lane] = hU;                 // h_final L0
        out[(size_t)Bb * Tt + bv * Hh + lane] = hV;

    } else if (wid == 1) {
        // ---- Warp B2: u-dots (bias1 folded) for both seqs + output stage ----
        unsigned long long wu[16];
        load_w2(W_ih1, lane, wu);
        const float bias1 = b_ih1[lane] + b_hh1[lane];
        float wc[Hh];
        const float bo = b_out[0];
        #pragma unroll
        for (int k = 0; k < Hh; ++k) wc[k] = W_out[k];
        unsigned int s0u = (unsigned int)__cvta_generic_to_shared(sh0u);
        unsigned int s0v = (unsigned int)__cvta_generic_to_shared(sh0v);
        float* obU = out + (size_t)bu * Tt;
        float* obV = out + (size_t)bv * Tt;

        for (int g = 0; g < NCHUNK + 3; ++g) {
            if (g >= 1 && g <= NCHUNK) {
                int buf = (g - 1) & 1;
                unsigned int baseU = s0u + buf * RSZ;
                unsigned int baseV = s0v + buf * RSZ;
                #pragma unroll 4
                for (int s = 0; s < CHUNK; ++s) {
                    LOADPN(baseU + s * (Hh * 4), U);
                    LOADPN(baseV + s * (Hh * 4), V);
                    float uu; DOT16N(wu, bias1, uu, U);
                    float uv; DOT16N(wu, bias1, uv, V);
                    suu[buf][s][lane] = uu;
                    suv[buf][s][lane] = uv;
                }
            }
            if (g >= 3) {                           // out: lanes 0-15 seq U, 16-31 seq V
                int gg  = g - 3;
                int t   = lane & 15;
                const float* hv = (lane < 16) ? sh1u[gg & 1][t] : sh1v[gg & 1][t];
                float a0 = 0.f, a1 = 0.f, a2 = 0.f, a3 = 0.f;
                #pragma unroll
                for (int k = 0; k < 8; ++k) {
                    a0 = fmaf(wc[k],      hv[k],      a0);
                    a1 = fmaf(wc[k + 8],  hv[k + 8],  a1);
                    a2 = fmaf(wc[k + 16], hv[k + 16], a2);
                    a3 = fmaf(wc[k + 24], hv[k + 24], a3);
                }
                float o = ((a0 + a1) + (a2 + a3)) + bo;
                if (lane < 16) obU[gg * CHUNK + t] = o;
                else           obV[gg * CHUNK + t] = o;
            }
            __syncthreads();
        }

    } else {
        // ---- Warp B1: layer-1, two sequences (lags A by 2 chunks) ----
        unsigned long long w2[16];
        load_w2(W_hh1, lane, w2);
        float hU = h_state[Bb * Hh + bu * Hh + lane];
        float hV = h_state[Bb * Hh + bv * Hh + lane];
        unsigned int hxu = (unsigned int)__cvta_generic_to_shared(hx1u);
        unsigned int hxv = (unsigned int)__cvta_generic_to_shared(hx1v);
        unsigned int suua = (unsigned int)__cvta_generic_to_shared(suu);
        unsigned int suva = (unsigned int)__cvta_generic_to_shared(suv);
        STSF(hxu + lane * 4, hU);
        STSF(hxv + lane * 4, hV);
        for (int g = 0; g < NCHUNK + 3; ++g) {
            if (g >= 2 && g <= NCHUNK + 1) {
                int c = g - 2;
                unsigned int ubU = suua + (c & 1) * RSZ + lane * 4;
                unsigned int ubV = suva + (c & 1) * RSZ + lane * 4;
                float (*dU)[Hh + 1] = sh1u[c & 1];
                float (*dV)[Hh + 1] = sh1v[c & 1];
                #pragma unroll 8
                for (int s = 0; s < CHUNK; ++s) {
                    float uvU, uvV;
                    LDSF(uvU, ubU + s * (Hh * 4));  // off-chain seeds
                    LDSF(uvV, ubV + s * (Hh * 4));
                    LOADPN(hxu, U);                 // both exchange bursts first
                    LOADPN(hxv, V);
                    float zU; DOT16N(w2, uvU, zU, U);
                    float zV; DOT16N(w2, uvV, zV, V);
                    hU = htanh(zU);
                    hV = htanh(zV);
                    STSF(hxu + lane * 4, hU);       // exchange writes for next step
                    STSF(hxv + lane * 4, hV);
                    dU[s][lane] = hU;               // ring for out-stage
                    dV[s][lane] = hV;
                }
            }
            __syncthreads();
        }
        out[(size_t)Bb * Tt + Bb * Hh + bu * Hh + lane] = hU;       // h_final L1
        out[(size_t)Bb * Tt + Bb * Hh + bv * Hh + lane] = hV;
    }
}

extern "C" void kernel_launch(void* const* d_in, const int* in_sizes, int n_in,
                              void* d_out, int out_size) {
    (void)in_sizes; (void)n_in; (void)out_size;
    rnn_pipe_kernel<<<Bb / 2, 96>>>(
        (const float*)d_in[0],  (const float*)d_in[1],  (const float*)d_in[2],
        (const float*)d_in[3],  (const float*)d_in[4],  (const float*)d_in[5],
        (const float*)d_in[6],  (const float*)d_in[7],  (const float*)d_in[8],
        (const float*)d_in[9],  (const float*)d_in[10], (const float*)d_in[11],
        (float*)d_out);
}

// round 12
// speedup vs baseline: 1.6602x; 1.6602x over previous
#include <cuda_runtime.h>

#define Hh 32
#define Bb 64
#define Tt 16384
#define CHUNK 32
#define NCHUNK (Tt / CHUNK)

__device__ __forceinline__ unsigned long long pk2(float lo, float hi) {
    unsigned long long d; asm("mov.b64 %0,{%1,%2};" : "=l"(d) : "f"(lo), "f"(hi)); return d;
}
__device__ __forceinline__ void upk2(unsigned long long v, float& lo, float& hi) {
    asm("mov.b64 {%0,%1},%2;" : "=f"(lo), "=f"(hi) : "l"(v));
}
__device__ __forceinline__ unsigned long long ffma2(unsigned long long a, unsigned long long b, unsigned long long c) {
    unsigned long long d; asm("fma.rn.f32x2 %0,%1,%2,%3;" : "=l"(d) : "l"(a), "l"(b), "l"(c)); return d;
}
__device__ __forceinline__ unsigned long long fadd2(unsigned long long a, unsigned long long b) {
    unsigned long long d; asm("add.rn.f32x2 %0,%1,%2;" : "=l"(d) : "l"(a), "l"(b)); return d;
}
__device__ __forceinline__ float red2(unsigned long long a0, unsigned long long a1,
                                      unsigned long long a2, unsigned long long a3) {
    unsigned long long s = fadd2(fadd2(a0, a1), fadd2(a2, a3));
    float lo, hi; upk2(s, lo, hi);
    return lo + hi;
}

// hardware tanh (MUFU.TANH, lat ~16)
__device__ __forceinline__ float htanh(float z) {
    float t; asm("tanh.approx.f32 %0,%1;" : "=f"(t) : "f"(z));
    return t;
}

#define LOADPN(sa_, P) \
    unsigned long long P##0,P##1,P##2,P##3,P##4,P##5,P##6,P##7,P##8,P##9,P##a,P##b,P##c,P##d,P##e,P##f; \
    asm volatile("ld.shared.v2.u64 {%0,%1},[%2];"    : "=l"(P##0), "=l"(P##1) : "r"(sa_)); \
    asm volatile("ld.shared.v2.u64 {%0,%1},[%2+16];" : "=l"(P##2), "=l"(P##3) : "r"(sa_)); \
    asm volatile("ld.shared.v2.u64 {%0,%1},[%2+32];" : "=l"(P##4), "=l"(P##5) : "r"(sa_)); \
    asm volatile("ld.shared.v2.u64 {%0,%1},[%2+48];" : "=l"(P##6), "=l"(P##7) : "r"(sa_)); \
    asm volatile("ld.shared.v2.u64 {%0,%1},[%2+64];" : "=l"(P##8), "=l"(P##9) : "r"(sa_)); \
    asm volatile("ld.shared.v2.u64 {%0,%1},[%2+80];" : "=l"(P##a), "=l"(P##b) : "r"(sa_)); \
    asm volatile("ld.shared.v2.u64 {%0,%1},[%2+96];" : "=l"(P##c), "=l"(P##d) : "r"(sa_)); \
    asm volatile("ld.shared.v2.u64 {%0,%1},[%2+112];": "=l"(P##e), "=l"(P##f) : "r"(sa_));

#define DOT16N(w2, seed, res, P) { \
    unsigned long long a0 = pk2(seed, 0.f), a1 = 0ull, a2 = 0ull, a3 = 0ull; \
    a0 = ffma2(w2[0],  P##0, a0); a1 = ffma2(w2[1],  P##1, a1); \
    a2 = ffma2(w2[2],  P##2, a2); a3 = ffma2(w2[3],  P##3, a3); \
    a0 = ffma2(w2[4],  P##4, a0); a1 = ffma2(w2[5],  P##5, a1); \
    a2 = ffma2(w2[6],  P##6, a2); a3 = ffma2(w2[7],  P##7, a3); \
    a0 = ffma2(w2[8],  P##8, a0); a1 = ffma2(w2[9],  P##9, a1); \
    a2 = ffma2(w2[10], P##a, a2); a3 = ffma2(w2[11], P##b, a3); \
    a0 = ffma2(w2[12], P##c, a0); a1 = ffma2(w2[13], P##d, a1); \
    a2 = ffma2(w2[14], P##e, a2); a3 = ffma2(w2[15], P##f, a3); \
    res = red2(a0, a1, a2, a3); }

#define STSF(addr, val) asm volatile("st.shared.f32 [%0], %1;" :: "r"(addr), "f"(val))

// load packed weight rows (plain, unscaled)
__device__ __forceinline__ void load_w2(const float* __restrict__ W, int lane,
                                        unsigned long long* w2) {
    #pragma unroll
    for (int k = 0; k < 16; ++k)
        w2[k] = pk2(W[lane * Hh + 2 * k], W[lane * Hh + 2 * k + 1]);
}

__global__ __launch_bounds__(96, 1) void rnn_pipe_kernel(
    const float* __restrict__ x,        const float* __restrict__ h_state,
    const float* __restrict__ W_ih0,    const float* __restrict__ W_hh0,
    const float* __restrict__ b_ih0,    const float* __restrict__ b_hh0,
    const float* __restrict__ W_ih1,    const float* __restrict__ W_hh1,
    const float* __restrict__ b_ih1,    const float* __restrict__ b_hh1,
    const float* __restrict__ W_out,    const float* __restrict__ b_out,
    float* __restrict__ out)
{
    __shared__ __align__(16) float sh0[2][CHUNK][Hh];   // A -> B2 ring; ALSO A's step exchange
    __shared__ __align__(16) float su [2][CHUNK][Hh];   // B2 -> B1 (bias1 pre-folded)
    __shared__ float sh1[2][CHUNK][Hh + 1];             // B1 -> out stage (padded)
    __shared__ __align__(16) float hx1[Hh];             // warp B1 step exchange

    const int b    = blockIdx.x;
    const int lane = threadIdx.x & 31;
    const int wid  = threadIdx.x >> 5;
    const unsigned FULL = 0xffffffffu;

    if (wid == 0) {
        // ---- Warp A: layer-0 recurrence; exchange through the ring rows ----
        unsigned long long w2[16];
        load_w2(W_hh0, lane, w2);
        const float wi    = W_ih0[lane];
        const float bias0 = b_ih0[lane] + b_hh0[lane];
        float h = h_state[b * Hh + lane];
        unsigned int s0a = (unsigned int)__cvta_generic_to_shared(sh0);

        // Seed the exchange: pretend step -1 wrote buf1 row31 (overwritten in chunk 1
        // before B2 ever consumes chunk-1 data).
        unsigned int rd = s0a + (CHUNK * Hh * 4) + 31 * (Hh * 4);
        STSF(rd + lane * 4, h);

        const float* xb = x + (size_t)b * Tt;
        float xc = xb[lane];
        for (int g = 0; g < NCHUNK + 3; ++g) {
            if (g < NCHUNK) {
                float xn = (g + 1 < NCHUNK) ? xb[(g + 1) * CHUNK + lane] : 0.f;
                unsigned int wr = s0a + (g & 1) * (CHUNK * Hh * 4);
                #pragma unroll 16
                for (int s = 0; s < CHUNK; ++s) {
                    float xterm = fmaf(__shfl_sync(FULL, xc, s), wi, bias0); // off-chain
                    LOADPN(rd, U);                     // row written at step s-1
                    float z; DOT16N(w2, xterm, z, U);
                    h = htanh(z);
                    STSF(wr + lane * 4, h);            // chain STS doubles as ring write
                    rd = wr;
                    wr += Hh * 4;
                }
                xc = xn;
            }
            __syncthreads();
        }
        out[(size_t)Bb * Tt + b * Hh + lane] = h;                    // h_final L0

    } else if (wid == 1) {
        // ---- Warp B2: u-projection (bias1 folded) from h0 ring + output stage ----
        unsigned long long wu[16];
        load_w2(W_ih1, lane, wu);
        const float bias1 = b_ih1[lane] + b_hh1[lane];
        float wc[Hh];
        const float bo = b_out[0];
        #pragma unroll
        for (int k = 0; k < Hh; ++k) wc[k] = W_out[k];
        unsigned int s0a = (unsigned int)__cvta_generic_to_shared(sh0);
        float* ob = out + (size_t)b * Tt;

        for (int g = 0; g < NCHUNK + 3; ++g) {
            if (g >= 1 && g <= NCHUNK) {
                int buf = (g - 1) & 1;
                unsigned int base = s0a + buf * (CHUNK * Hh * 4);
                #pragma unroll 4
                for (int s = 0; s < CHUNK; ++s) {
                    LOADPN(base + s * (Hh * 4), U);
                    float uu; DOT16N(wu, bias1, uu, U);
                    su[buf][s][lane] = uu;
                }
            }
            if (g >= 3) {                               // output stage
                int gg  = g - 3;
                const float* hv = sh1[gg & 1][lane];    // lane = timestep in chunk
                float a0 = 0.f, a1 = 0.f, a2 = 0.f, a3 = 0.f;
                #pragma unroll
                for (int k = 0; k < 8; ++k) {
                    a0 = fmaf(wc[k],      hv[k],      a0);
                    a1 = fmaf(wc[k + 8],  hv[k + 8],  a1);
                    a2 = fmaf(wc[k + 16], hv[k + 16], a2);
                    a3 = fmaf(wc[k + 24], hv[k + 24], a3);
                }
                ob[gg * CHUNK + lane] = (((a0 + a1) + (a2 + a3)) + bo);
            }
            __syncthreads();
        }

    } else {
        // ---- Warp B1: layer-1 recurrence (lags A by 2 chunks) ----
        unsigned long long w2[16];
        load_w2(W_hh1, lane, w2);
        float h = h_state[Bb * Hh + b * Hh + lane];
        unsigned int hx1a = (unsigned int)__cvta_generic_to_shared(hx1);
        for (int g = 0; g < NCHUNK + 3; ++g) {
            if (g >= 2 && g <= NCHUNK + 1) {
                int c = g - 2;
                int buf = c & 1;                        // su buffer for chunk c
                float (*dst)[Hh + 1] = sh1[c & 1];
                const float* sv = su[buf][0];           // seeds: plain loads, hoistable
                #pragma unroll 16
                for (int s = 0; s < CHUNK; ++s) {
                    float uv = sv[s * Hh + lane];       // off-chain, non-volatile -> batched
                    STSF(hx1a + lane * 4, h);
                    LOADPN(hx1a, U);
                    float z; DOT16N(w2, uv, z, U);
                    h = htanh(z);
                    dst[s][lane] = h;
                }
            }
            __syncthreads();
        }
        out[(size_t)Bb * Tt + Bb * Hh + b * Hh + lane] = h;          // h_final L1
    }
}

extern "C" void kernel_launch(void* const* d_in, const int* in_sizes, int n_in,
                              void* d_out, int out_size) {
    (void)in_sizes; (void)n_in; (void)out_size;
    rnn_pipe_kernel<<<Bb, 96>>>(
        (const float*)d_in[0],  (const float*)d_in[1],  (const float*)d_in[2],
        (const float*)d_in[3],  (const float*)d_in[4],  (const float*)d_in[5],
        (const float*)d_in[6],  (const float*)d_in[7],  (const float*)d_in[8],
        (const float*)d_in[9],  (const float*)d_in[10], (const float*)d_in[11],
        (float*)d_out);
}